// round 8
// baseline (speedup 1.0000x reference)
#include <cuda_runtime.h>
#include <cuda_fp16.h>
#include <cstdint>

#define BB 64
#define TT 2000
#define QD 1024
#define MD 512
#define AD 128
#define NF 32
#define KW 31
#define TTILE 128

// smem byte offsets (half tiles: 128 rows x 32 halves = 64B/row = 8KB)
#define OFF_A0 0
#define OFF_A1 8192
#define OFF_B0 16384
#define OFF_B1 24576
#define OFF_AWC 32768
#define OFF_PQ  34048
#define OFF_V   34560
#define OFF_ERED 35072
#define SMEM_TOT 37120

__device__ float  g_pq[BB * AD];
__device__ __half g_WmT[AD * MD];   // Wm transposed to [a][k], k contiguous

__device__ __forceinline__ float fast_tanh(float x) {
    x = fminf(15.0f, fmaxf(-15.0f, x));
    float e = __expf(2.0f * x);
    return (e - 1.0f) * __frcp_rn(e + 1.0f);
}

// byte offset of half2 (row r, half2-col c) in a 64B-row swizzled tile.
// banks (16r + c^((r>>1&3)<<2)) % 32: perfect partition for all frag patterns.
__device__ __forceinline__ uint32_t swz(int r, int c) {
    return (uint32_t)(r * 64 + ((c ^ (((r >> 1) & 3) << 2)) << 2));
}

__device__ __forceinline__ uint32_t f2h2(float a, float b) {
    __half2 h = __floats2half2_rn(a, b);
    return *reinterpret_cast<uint32_t*>(&h);
}

__device__ __forceinline__ void cpa16(uint32_t s, const void* g) {
    asm volatile("cp.async.cg.shared.global [%0], [%1], 16;" :: "r"(s), "l"(g));
}

__device__ __forceinline__ void mma16(float* c, const uint32_t* a, uint32_t b0, uint32_t b1) {
    asm volatile(
        "mma.sync.aligned.m16n8k16.row.col.f32.f16.f16.f32 "
        "{%0,%1,%2,%3}, {%4,%5,%6,%7}, {%8,%9}, {%0,%1,%2,%3};"
        : "+f"(c[0]), "+f"(c[1]), "+f"(c[2]), "+f"(c[3])
        : "r"(a[0]), "r"(a[1]), "r"(a[2]), "r"(a[3]), "r"(b0), "r"(b1));
}

// one K=32 chunk (2 x k16 steps) of D[128t x 128a] += A x B^T
__device__ __forceinline__ void mma_chunk(const char* At, const char* Bt,
                                          int wm, int wn, int g, int j,
                                          float acc[4][4][4]) {
#pragma unroll
    for (int ks = 0; ks < 2; ks++) {
        const int cb = 8 * ks;
        uint32_t af[4][4];
#pragma unroll
        for (int mt = 0; mt < 4; mt++) {
            int r0 = wm * 64 + mt * 16 + g;
            af[mt][0] = *(const uint32_t*)(At + swz(r0,     cb + j));
            af[mt][1] = *(const uint32_t*)(At + swz(r0 + 8, cb + j));
            af[mt][2] = *(const uint32_t*)(At + swz(r0,     cb + j + 4));
            af[mt][3] = *(const uint32_t*)(At + swz(r0 + 8, cb + j + 4));
        }
#pragma unroll
        for (int nt = 0; nt < 4; nt++) {
            int n = wn * 32 + nt * 8 + g;
            uint32_t b0 = *(const uint32_t*)(Bt + swz(n, cb + j));
            uint32_t b1 = *(const uint32_t*)(Bt + swz(n, cb + j + 4));
#pragma unroll
            for (int mt = 0; mt < 4; mt++)
                mma16(acc[mt][nt], af[mt], b0, b1);
        }
    }
}

// ---------------- Kernel 0: Wm -> g_WmT half [a][k] --------------------------
__global__ void k_prep(const float* __restrict__ Wm) {
    int i = blockIdx.x * 256 + threadIdx.x;   // over 512*128
    int k = i >> 7, a = i & 127;
    g_WmT[a * MD + k] = __float2half_rn(Wm[i]);
}

// ---------------- Kernel 1: pq = tanh(query @ Wq), zero context --------------
__global__ void k_pq(const float* __restrict__ q, const float* __restrict__ Wq,
                     float* __restrict__ ctx) {
    __shared__ float qs[QD];
    int b = blockIdx.x;
    for (int i = threadIdx.x; i < QD; i += 128) qs[i] = q[b * QD + i];
    for (int i = threadIdx.x; i < MD; i += 128) ctx[b * MD + i] = 0.0f;
    __syncthreads();
    int a = threadIdx.x;
    float acc = 0.0f;
#pragma unroll 8
    for (int k = 0; k < QD; k++) acc += qs[k] * Wq[k * AD + a];
    g_pq[b * AD + a] = fast_tanh(acc);
}

// ---------------- Kernel 2: fused energies (fp16 m16n8k16) -------------------
// grid (16, 64), 256 threads (8 warps: 2 M x 4 N)
__global__ void __launch_bounds__(256, 1)
k_energies(const float* __restrict__ mem, const float* __restrict__ awc,
           const float* __restrict__ ck, const float* __restrict__ Wloc,
           const float* __restrict__ Vv, float* __restrict__ ener) {
    __shared__ __align__(1024) char smc[SMEM_TOT];
    const uint32_t smu = (uint32_t)__cvta_generic_to_shared(smc);

    const int b  = blockIdx.y;
    const int t0 = blockIdx.x * TTILE;
    const int tid = threadIdx.x;
    const int lane = tid & 31, w = tid >> 5;
    const int wm = w >> 2, wn = w & 3;
    const int g = lane >> 2, j = lane & 3;

    float* awcs = (float*)(smc + OFF_AWC);
    float* pqs  = (float*)(smc + OFF_PQ);
    float* Vs   = (float*)(smc + OFF_V);
    float* ered = (float*)(smc + OFF_ERED);

    // A staging coords: thread covers row r, floats h*16..h*16+15
    const int ar = tid >> 1, ah = tid & 1;
    const bool av = (t0 + ar) < TT;
    const float* asrc = mem + ((size_t)(b * TT + t0 + ar)) * MD + ah * 16;

    // ---- prologue: LDG A chunk0 + cp.async B chunk0 -> buf0 ----
    float4 ra[4];
    const float4 z4 = make_float4(0.f, 0.f, 0.f, 0.f);
#pragma unroll
    for (int q = 0; q < 4; q++) ra[q] = av ? *(const float4*)(asrc + q * 4) : z4;
#pragma unroll
    for (int p = 0; p < 2; p++) {
        int s = tid + p * 256;
        int rB = s >> 2, qs4 = (s & 3) * 4;
        cpa16(smu + OFF_B0 + swz(rB, qs4), g_WmT + rB * MD + qs4 * 2);
    }
    asm volatile("cp.async.commit_group;" ::: "memory");

    // ---- small loads ----
    if (tid < AD) { pqs[tid] = g_pq[b * AD + tid]; Vs[tid] = Vv[tid]; }
    for (int i = tid; i < 2 * 160; i += 256) {
        int c = i / 160, tl = i % 160;
        int t = t0 - 15 + tl;
        awcs[i] = (t >= 0 && t < TT) ? awc[(b * 2 + c) * TT + t] : 0.0f;
    }

    // ---- cvt+store A chunk0 -> buf0 ----
    {
        uint4 u0, u1;
        u0.x = f2h2(ra[0].x, ra[0].y); u0.y = f2h2(ra[0].z, ra[0].w);
        u0.z = f2h2(ra[1].x, ra[1].y); u0.w = f2h2(ra[1].z, ra[1].w);
        u1.x = f2h2(ra[2].x, ra[2].y); u1.y = f2h2(ra[2].z, ra[2].w);
        u1.z = f2h2(ra[3].x, ra[3].y); u1.w = f2h2(ra[3].z, ra[3].w);
        *(uint4*)(smc + OFF_A0 + swz(ar, 8 * ah))     = u0;
        *(uint4*)(smc + OFF_A0 + swz(ar, 8 * ah + 4)) = u1;
    }
    __syncthreads();   // awcs visible

    // ---- conv -> A1 (half), WlocT -> B1 (half) ----
    for (int i = tid; i < TTILE * NF; i += 256) {
        int tl = i >> 5, f = i & 31;
        float acc = 0.0f;
#pragma unroll
        for (int k = 0; k < KW; k++) {
            acc += awcs[tl + k]       * ck[(k * 2 + 0) * NF + f];
            acc += awcs[160 + tl + k] * ck[(k * 2 + 1) * NF + f];
        }
        *(__half*)(smc + OFF_A1 + swz(tl, f >> 1) + 2 * (f & 1)) = __float2half_rn(acc);
    }
    for (int i = tid; i < AD * NF; i += 256) {
        int a = i >> 5, f = i & 31;
        *(__half*)(smc + OFF_B1 + swz(a, f >> 1) + 2 * (f & 1)) =
            __float2half_rn(Wloc[f * AD + a]);
    }
    asm volatile("cp.async.wait_group 0;" ::: "memory");
    __syncthreads();   // buf0 + buf1 fully resident

    // ---- loc GEMM (K=32, one chunk) from buf1 ----
    float locf[4][4][4];
#pragma unroll
    for (int mt = 0; mt < 4; mt++)
#pragma unroll
        for (int nt = 0; nt < 4; nt++)
#pragma unroll
            for (int r = 0; r < 4; r++) locf[mt][nt][r] = 0.0f;
    mma_chunk(smc + OFF_A1, smc + OFF_B1, wm, wn, g, j, locf);

#pragma unroll
    for (int mt = 0; mt < 4; mt++)
#pragma unroll
        for (int nt = 0; nt < 4; nt++) {
            int col0 = wn * 32 + nt * 8 + 2 * j;
            float p0 = pqs[col0], p1 = pqs[col0 + 1];
            locf[mt][nt][0] = fast_tanh(locf[mt][nt][0]) + p0;
            locf[mt][nt][1] = fast_tanh(locf[mt][nt][1]) + p1;
            locf[mt][nt][2] = fast_tanh(locf[mt][nt][2]) + p0;
            locf[mt][nt][3] = fast_tanh(locf[mt][nt][3]) + p1;
        }
    __syncthreads();   // all warps done reading buf1 before iter0 overwrites it

    // ---- pm GEMM: 16 K=32 chunks, double buffered ----
    float acc[4][4][4];
#pragma unroll
    for (int mt = 0; mt < 4; mt++)
#pragma unroll
        for (int nt = 0; nt < 4; nt++)
#pragma unroll
            for (int r = 0; r < 4; r++) acc[mt][nt][r] = 0.0f;

    for (int it = 0; it < 16; it++) {
        const uint32_t curA = (it & 1) ? OFF_A1 : OFF_A0;
        const uint32_t curB = (it & 1) ? OFF_B1 : OFF_B0;
        const uint32_t nxtA = (it & 1) ? OFF_A0 : OFF_A1;
        const uint32_t nxtB = (it & 1) ? OFF_B0 : OFF_B1;
        if (it < 15) {
            const int kc = (it + 1) * 32;
#pragma unroll
            for (int q = 0; q < 4; q++)
                ra[q] = av ? *(const float4*)(asrc + kc + q * 4) : z4;
#pragma unroll
            for (int p = 0; p < 2; p++) {
                int s = tid + p * 256;
                int rB = s >> 2, qs4 = (s & 3) * 4;
                cpa16(smu + nxtB + swz(rB, qs4), g_WmT + rB * MD + kc + qs4 * 2);
            }
            asm volatile("cp.async.commit_group;" ::: "memory");
        }

        mma_chunk(smc + curA, smc + curB, wm, wn, g, j, acc);

        if (it < 15) {
            uint4 u0, u1;
            u0.x = f2h2(ra[0].x, ra[0].y); u0.y = f2h2(ra[0].z, ra[0].w);
            u0.z = f2h2(ra[1].x, ra[1].y); u0.w = f2h2(ra[1].z, ra[1].w);
            u1.x = f2h2(ra[2].x, ra[2].y); u1.y = f2h2(ra[2].z, ra[2].w);
            u1.z = f2h2(ra[3].x, ra[3].y); u1.w = f2h2(ra[3].z, ra[3].w);
            *(uint4*)(smc + nxtA + swz(ar, 8 * ah))     = u0;
            *(uint4*)(smc + nxtA + swz(ar, 8 * ah + 4)) = u1;
            asm volatile("cp.async.wait_group 0;" ::: "memory");
        }
        __syncthreads();
    }

    // ---- epilogue: e[t] = sum_a V[a]*tanh(tanh(loc)+pq+tanh(pm)) ----
#pragma unroll
    for (int mt = 0; mt < 4; mt++) {
        float p0 = 0.0f, p1 = 0.0f;
#pragma unroll
        for (int nt = 0; nt < 4; nt++) {
            int col0 = wn * 32 + nt * 8 + 2 * j;
            float v0 = Vs[col0], v1 = Vs[col0 + 1];
            p0 += v0 * fast_tanh(locf[mt][nt][0] + fast_tanh(acc[mt][nt][0]));
            p0 += v1 * fast_tanh(locf[mt][nt][1] + fast_tanh(acc[mt][nt][1]));
            p1 += v0 * fast_tanh(locf[mt][nt][2] + fast_tanh(acc[mt][nt][2]));
            p1 += v1 * fast_tanh(locf[mt][nt][3] + fast_tanh(acc[mt][nt][3]));
        }
        p0 += __shfl_xor_sync(0xffffffffu, p0, 1);
        p0 += __shfl_xor_sync(0xffffffffu, p0, 2);
        p1 += __shfl_xor_sync(0xffffffffu, p1, 1);
        p1 += __shfl_xor_sync(0xffffffffu, p1, 2);
        if (j == 0) {
            int r = wm * 64 + mt * 16 + g;
            ered[wn * 128 + r] = p0;
            ered[wn * 128 + r + 8] = p1;
        }
    }
    __syncthreads();
    if (tid < TTILE) {
        int t = t0 + tid;
        if (t < TT)
            ener[b * TT + t] = ered[tid] + ered[128 + tid] + ered[256 + tid] + ered[384 + tid];
    }
}

// ---------------- Kernel 3: softmax over T per batch row ---------------------
__global__ void k_softmax(float* __restrict__ wts) {
    __shared__ float red[256];
    const int b = blockIdx.x, tid = threadIdx.x;
    float* e = wts + b * TT;
    float v[8];
    float mx = -1e30f;
#pragma unroll
    for (int i = 0; i < 8; i++) {
        int t = tid + i * 256;
        v[i] = (t < TT) ? e[t] : -1e30f;
        mx = fmaxf(mx, v[i]);
    }
    red[tid] = mx; __syncthreads();
    for (int s = 128; s > 0; s >>= 1) {
        if (tid < s) red[tid] = fmaxf(red[tid], red[tid + s]);
        __syncthreads();
    }
    mx = red[0]; __syncthreads();
    float sum = 0.0f;
#pragma unroll
    for (int i = 0; i < 8; i++) {
        int t = tid + i * 256;
        v[i] = (t < TT) ? __expf(v[i] - mx) : 0.0f;
        sum += v[i];
    }
    red[tid] = sum; __syncthreads();
    for (int s = 128; s > 0; s >>= 1) {
        if (tid < s) red[tid] += red[tid + s];
        __syncthreads();
    }
    float inv = 1.0f / red[0];
#pragma unroll
    for (int i = 0; i < 8; i++) {
        int t = tid + i * 256;
        if (t < TT) e[t] = v[i] * inv;
    }
}

// ---------------- Kernel 4: context = w @ memory -----------------------------
__global__ void k_context(const float* __restrict__ mem, const float* __restrict__ wts,
                          float* __restrict__ ctx) {
    __shared__ float ws[200];
    const int b = blockIdx.y, tid = threadIdx.x;
    const int tstart = blockIdx.x * 200;
    if (tid < 200) ws[tid] = wts[b * TT + tstart + tid];
    __syncthreads();
    const int d = (tid & 127) * 4;
    const int r0 = tid >> 7;
    const float* mp = mem + ((size_t)(b * TT + tstart + r0)) * MD + d;
    float ax = 0.f, ay = 0.f, az = 0.f, aw = 0.f;
#pragma unroll 4
    for (int t = 0; t < 200; t += 2) {
        float4 m = *(const float4*)(mp + (size_t)t * MD);
        float wv = ws[t + r0];
        ax += wv * m.x; ay += wv * m.y; az += wv * m.z; aw += wv * m.w;
    }
    atomicAdd(&ctx[b * MD + d + 0], ax);
    atomicAdd(&ctx[b * MD + d + 1], ay);
    atomicAdd(&ctx[b * MD + d + 2], az);
    atomicAdd(&ctx[b * MD + d + 3], aw);
}

// ---------------- launch -----------------------------------------------------
extern "C" void kernel_launch(void* const* d_in, const int* in_sizes, int n_in,
                              void* d_out, int out_size) {
    const float* q    = (const float*)d_in[0];
    const float* mem  = (const float*)d_in[1];
    const float* awc  = (const float*)d_in[2];
    const float* Wq   = (const float*)d_in[3];
    const float* Wm   = (const float*)d_in[4];
    const float* ck   = (const float*)d_in[5];
    const float* Wloc = (const float*)d_in[6];
    const float* V    = (const float*)d_in[7];

    float* ctx = (float*)d_out;            // [64, 512]
    float* wts = (float*)d_out + BB * MD;  // [64, 2000]

    k_prep<<<(AD * MD) / 256, 256>>>(Wm);
    k_pq<<<BB, 128>>>(q, Wq, ctx);
    dim3 gE(16, BB);
    k_energies<<<gE, 256>>>(mem, awc, ck, Wloc, V, wts);
    k_softmax<<<BB, 256>>>(wts);
    dim3 gC(10, BB);
    k_context<<<gC, 256>>>(mem, wts, ctx);
}